// round 9
// baseline (speedup 1.0000x reference)
#include <cuda_runtime.h>

#define BQ 64
#define NQ 64
#define TQ 4096
#define BN (BQ * NQ)     // 4096 floats per time slice
#define CCH 16           // chunks
#define LCH 256          // chunk length (CCH*LCH == TQ)

// Scratch: E = exp(emissions) in [t][b][j] layout; alpha (linear, scaled);
// u = alpha*beta (linear, per-(b,t) uniform scale — cancels in gamma).
__device__ float g_E[TQ * BN];
__device__ float g_alpha[TQ * BN];
__device__ float g_u[TQ * BN];

// ---- packed f32x2 helpers ----
__device__ __forceinline__ void fma2(unsigned long long& d,
                                     unsigned long long a, unsigned long long b) {
    asm("fma.rn.f32x2 %0, %1, %2, %0;" : "+l"(d) : "l"(a), "l"(b));
}
__device__ __forceinline__ unsigned long long add2(unsigned long long a,
                                                   unsigned long long b) {
    unsigned long long d;
    asm("add.rn.f32x2 %0, %1, %2;" : "=l"(d) : "l"(a), "l"(b));
    return d;
}
__device__ __forceinline__ unsigned long long pack2(float lo, float hi) {
    unsigned long long d;
    asm("mov.b64 %0, {%1, %2};" : "=l"(d) : "f"(lo), "f"(hi));
    return d;
}
__device__ __forceinline__ float2 unpack2(unsigned long long v) {
    float2 r;
    asm("mov.b64 {%0, %1}, %2;" : "=f"(r.x), "=f"(r.y) : "l"(v));
    return r;
}

// ---------------------------------------------------------------------------
// Kernel 1: E[t][b][j] = exp(emissions[b][j][t])  (tiled transpose via shared)
// ---------------------------------------------------------------------------
__global__ void __launch_bounds__(256) expT_kernel(const float* __restrict__ em) {
    __shared__ float tile[64][65];
    int b  = blockIdx.y;
    int t0 = blockIdx.x * 64;
    int tid = threadIdx.x;
    int c  = tid & 63;
    int r4 = tid >> 6;

#pragma unroll
    for (int rep = 0; rep < 16; rep++) {
        int j = rep * 4 + r4;
        tile[j][c] = __expf(em[b * NQ * TQ + j * TQ + t0 + c]);
    }
    __syncthreads();
#pragma unroll
    for (int rep = 0; rep < 16; rep++) {
        int tt = rep * 4 + r4;
        g_E[(t0 + tt) * BN + b * NQ + c] = tile[c][tt];
    }
}

// ---------------------------------------------------------------------------
// Shared scan machinery. 64 threads, 1 state/thread, 64-term dot as 32 f32x2
// FMAs. Renorm every 32 steps (REDUCE publishes partials at group pos +6,
// APPLY multiplies by 1/s at pos +7, only in the 4th group of each quad).
// E (and alpha, bwd) prefetched in 8 named register slots at distance 8.
// ---------------------------------------------------------------------------

#define DOT_FULL(PBUF)                                                         \
    const ulonglong2* pv = (const ulonglong2*)&psh[PBUF][0];                   \
    unsigned long long ac0 = 0, ac1 = 0, ac2 = 0, ac3 = 0;                     \
    _Pragma("unroll")                                                          \
    for (int k = 0; k < 16; k++) {                                             \
        ulonglong2 q = pv[k];                                                  \
        fma2((k & 1) ? ac2 : ac0, q.x, Apk[2 * k]);                            \
        fma2((k & 1) ? ac3 : ac1, q.y, Apk[2 * k + 1]);                        \
    }                                                                          \
    float2 fr = unpack2(add2(add2(ac0, ac1), add2(ac2, ac3)));                 \
    float v2 = fr.x + fr.y;

#define REDUCE_PUB()                                                           \
    {                                                                          \
        float s = v2;                                                          \
        s += __shfl_xor_sync(0xffffffffu, s, 1);                               \
        s += __shfl_xor_sync(0xffffffffu, s, 2);                               \
        s += __shfl_xor_sync(0xffffffffu, s, 4);                               \
        s += __shfl_xor_sync(0xffffffffu, s, 8);                               \
        s += __shfl_xor_sync(0xffffffffu, s, 16);                              \
        if (lane == 0) red[w] = s;                                             \
    }

// ----------------------------- forward ------------------------------------
#define FWD_STEP(T, EREG, APPLY, REDUCE) do {                                  \
    int tt_ = (T);                                                             \
    float e_new = g_E[((tt_ + 8 < TQ) ? tt_ + 8 : TQ - 1) * BN + ebase];       \
    if (APPLY) inv_s = __frcp_rn(red[0] + red[1]);                             \
    DOT_FULL((tt_ - 1) & 1)                                                    \
    if (APPLY) v2 *= inv_s;                                                    \
    v2 *= (EREG);                                                              \
    if (REDUCE) REDUCE_PUB()                                                   \
    if (tt_ >= wst) g_alpha[tt_ * BN + ebase] = v2;                            \
    psh[tt_ & 1][j] = v2;                                                      \
    __syncthreads();                                                           \
    (EREG) = e_new;                                                            \
} while (0)

#define FWD_G8(TB, RED) do {                                                   \
    FWD_STEP((TB),     e7, 0, 0);   FWD_STEP((TB) + 1, e0, 0, 0);              \
    FWD_STEP((TB) + 2, e1, 0, 0);   FWD_STEP((TB) + 3, e2, 0, 0);              \
    FWD_STEP((TB) + 4, e3, 0, 0);   FWD_STEP((TB) + 5, e4, 0, 0);              \
    FWD_STEP((TB) + 6, e5, 0, RED); FWD_STEP((TB) + 7, e6, RED, 0);            \
} while (0)

__global__ void __launch_bounds__(64) fwd_kernel(const float* __restrict__ trans,
                                                 const float* __restrict__ init) {
    const int c    = blockIdx.x;     // chunk
    const int b    = blockIdx.y;     // batch
    const int j    = threadIdx.x;    // state
    const int lane = j & 31;
    const int w    = j >> 5;

    __shared__ __align__(16) float psh[2][64];
    __shared__ float red[2];

    // column j of A, packed: Apk[2k]=(A[4k][j],A[4k+1][j]), Apk[2k+1]=(A[4k+2][j],A[4k+3][j])
    unsigned long long Apk[32];
#pragma unroll
    for (int k = 0; k < 16; k++) {
        int i0 = 4 * k;
        Apk[2 * k]     = pack2(trans[(i0    ) * NQ + j], trans[(i0 + 1) * NQ + j]);
        Apk[2 * k + 1] = pack2(trans[(i0 + 2) * NQ + j], trans[(i0 + 3) * NQ + j]);
    }

    const int ebase = b * NQ + j;
    const int wst = c * LCH;
    float inv_s = 1.0f;

    int t1, Gq, Gr;
    if (c == 0) {
        float v0 = init[j] * g_E[0 * BN + ebase];
        g_alpha[0 * BN + ebase] = v0;
        psh[0][j] = v0;
        t1 = 1;  Gq = 7;  Gr = 3;        // 7 + 31*8 = 255 steps: t = 1..255
    } else {
        t1 = c * LCH - 39;               // 39-step warmup from all-ones
        psh[(t1 - 1) & 1][j] = 1.0f;
        Gq = 9;  Gr = 0;                 // 7 + 36*8 = 295 steps
    }
    float e0 = g_E[(t1    ) * BN + ebase], e1 = g_E[(t1 + 1) * BN + ebase];
    float e2 = g_E[(t1 + 2) * BN + ebase], e3 = g_E[(t1 + 3) * BN + ebase];
    float e4 = g_E[(t1 + 4) * BN + ebase], e5 = g_E[(t1 + 5) * BN + ebase];
    float e6 = g_E[(t1 + 6) * BN + ebase], e7 = g_E[(t1 + 7) * BN + ebase];
    __syncthreads();

    // INIT7 (no renorm)
    FWD_STEP(t1,     e0, 0, 0); FWD_STEP(t1 + 1, e1, 0, 0);
    FWD_STEP(t1 + 2, e2, 0, 0); FWD_STEP(t1 + 3, e3, 0, 0);
    FWD_STEP(t1 + 4, e4, 0, 0); FWD_STEP(t1 + 5, e5, 0, 0);
    FWD_STEP(t1 + 6, e6, 0, 0);

    for (int q = 0; q < Gq; q++) {       // quads: renorm in 4th group only
        int t = t1 + 7 + 32 * q;
        FWD_G8(t, 0); FWD_G8(t + 8, 0); FWD_G8(t + 16, 0); FWD_G8(t + 24, 1);
    }
    for (int g = 0; g < Gr; g++) {       // remainder groups renorm each
        int t = t1 + 7 + 32 * Gq + 8 * g;
        FWD_G8(t, 1);
    }
}

// ----------------------------- backward ------------------------------------
// Writes u = alpha*beta (fused; beta never hits HBM).
#define BWD_STEP(T, EREG, AREG, APPLY, REDUCE) do {                            \
    int tt_ = (T);                                                             \
    int tp_ = (tt_ >= 8) ? tt_ - 8 : 0;                                        \
    float e_new = g_E[tp_ * BN + ebase];                                       \
    float a_new = g_alpha[tp_ * BN + ebase];                                   \
    if (APPLY) inv_s = __frcp_rn(red[0] + red[1]);                             \
    DOT_FULL((tt_ + 1) & 1)                                                    \
    if (APPLY) v2 *= inv_s;                                                    \
    if (REDUCE) REDUCE_PUB()                                                   \
    if (tt_ <= wend) g_u[tt_ * BN + ebase] = v2 * (AREG);                      \
    psh[tt_ & 1][j] = v2 * (EREG);                                             \
    __syncthreads();                                                           \
    (EREG) = e_new;                                                            \
    (AREG) = a_new;                                                            \
} while (0)

#define BWD_G8(TB, RED) do {                                                   \
    BWD_STEP((TB),     e7, a7, 0, 0);   BWD_STEP((TB) - 1, e0, a0, 0, 0);      \
    BWD_STEP((TB) - 2, e1, a1, 0, 0);   BWD_STEP((TB) - 3, e2, a2, 0, 0);      \
    BWD_STEP((TB) - 4, e3, a3, 0, 0);   BWD_STEP((TB) - 5, e4, a4, 0, 0);      \
    BWD_STEP((TB) - 6, e5, a5, 0, RED); BWD_STEP((TB) - 7, e6, a6, RED, 0);    \
} while (0)

__global__ void __launch_bounds__(64) bwd_kernel(const float* __restrict__ trans) {
    const int c    = blockIdx.x;
    const int b    = blockIdx.y;
    const int j    = threadIdx.x;
    const int lane = j & 31;
    const int w    = j >> 5;

    __shared__ __align__(16) float psh[2][64];
    __shared__ float red[2];

    // row j of A (contiguous), packed in source-pair order
    unsigned long long Apk[32];
    const float4* rp = (const float4*)(trans + j * NQ);
#pragma unroll
    for (int k = 0; k < 16; k++) {
        float4 a = rp[k];
        Apk[2 * k]     = pack2(a.x, a.y);
        Apk[2 * k + 1] = pack2(a.z, a.w);
    }

    const int ebase = b * NQ + j;
    const int wend = (c + 1) * LCH - 1;
    float inv_s = 1.0f;

    int te, Gq, Gr;
    if (c == CCH - 1) {
        te = TQ - 1;
        g_u[te * BN + ebase] = g_alpha[te * BN + ebase];   // beta_T = 1
        psh[te & 1][j] = g_E[te * BN + ebase];             // carry = beta*E
        Gq = 7;  Gr = 3;                                   // 255 steps
    } else {
        te = (c + 1) * LCH + 39;                           // warmup start
        psh[te & 1][j] = g_E[te * BN + ebase];             // beta = ones at te
        Gq = 9;  Gr = 0;                                   // 295 steps
    }
    int t1 = te - 1;
    float e0 = g_E[(t1    ) * BN + ebase], e1 = g_E[(t1 - 1) * BN + ebase];
    float e2 = g_E[(t1 - 2) * BN + ebase], e3 = g_E[(t1 - 3) * BN + ebase];
    float e4 = g_E[(t1 - 4) * BN + ebase], e5 = g_E[(t1 - 5) * BN + ebase];
    float e6 = g_E[(t1 - 6) * BN + ebase], e7 = g_E[(t1 - 7) * BN + ebase];
    float a0 = g_alpha[(t1    ) * BN + ebase], a1 = g_alpha[(t1 - 1) * BN + ebase];
    float a2 = g_alpha[(t1 - 2) * BN + ebase], a3 = g_alpha[(t1 - 3) * BN + ebase];
    float a4 = g_alpha[(t1 - 4) * BN + ebase], a5 = g_alpha[(t1 - 5) * BN + ebase];
    float a6 = g_alpha[(t1 - 6) * BN + ebase], a7 = g_alpha[(t1 - 7) * BN + ebase];
    __syncthreads();

    // INIT7 (no renorm)
    BWD_STEP(t1,     e0, a0, 0, 0); BWD_STEP(t1 - 1, e1, a1, 0, 0);
    BWD_STEP(t1 - 2, e2, a2, 0, 0); BWD_STEP(t1 - 3, e3, a3, 0, 0);
    BWD_STEP(t1 - 4, e4, a4, 0, 0); BWD_STEP(t1 - 5, e5, a5, 0, 0);
    BWD_STEP(t1 - 6, e6, a6, 0, 0);

    for (int q = 0; q < Gq; q++) {
        int t = t1 - 7 - 32 * q;
        BWD_G8(t, 0); BWD_G8(t - 8, 0); BWD_G8(t - 16, 0); BWD_G8(t - 24, 1);
    }
    for (int g = 0; g < Gr; g++) {
        int t = t1 - 7 - 32 * Gq - 8 * g;
        BWD_G8(t, 1);
    }
}

// ---------------------------------------------------------------------------
// Kernel 4: gamma from u (linear). out = log(u_j) - log(sum_j u_j).
// Tiled so output writes coalesce along t.
// ---------------------------------------------------------------------------
__global__ void __launch_bounds__(256) gamma_kernel(float* __restrict__ out) {
    __shared__ float gsh[64][33];
    __shared__ float part[8][32];
    __shared__ float lse[32];

    int b   = blockIdx.y;
    int t0  = blockIdx.x * 32;
    int tid = threadIdx.x;
    int c   = tid & 63;
    int r   = tid >> 6;

#pragma unroll
    for (int rep = 0; rep < 8; rep++) {
        int tt  = rep * 4 + r;
        gsh[c][tt] = g_u[(t0 + tt) * BN + b * NQ + c];
    }
    __syncthreads();

    int tt  = tid & 31;
    int seg = tid >> 5;

    float ss = 0.f;
#pragma unroll
    for (int k = 0; k < 8; k++) ss += gsh[seg * 8 + k][tt];
    part[seg][tt] = ss;
    __syncthreads();

    if (seg == 0) {
        float s = part[0][tt];
#pragma unroll
        for (int k = 1; k < 8; k++) s += part[k][tt];
        lse[tt] = __logf(s);
    }
    __syncthreads();

    float l = lse[tt];
#pragma unroll
    for (int rep = 0; rep < 8; rep++) {
        int jj = rep * 8 + seg;
        out[b * NQ * TQ + jj * TQ + t0 + tt] = __logf(gsh[jj][tt]) - l;
    }
}

// ---------------------------------------------------------------------------
extern "C" void kernel_launch(void* const* d_in, const int* in_sizes, int n_in,
                              void* d_out, int out_size) {
    const float* emissions = (const float*)d_in[0];   // [B, N, T]
    const float* init      = (const float*)d_in[1];   // [N]
    const float* trans     = (const float*)d_in[2];   // [N, N]
    float* out = (float*)d_out;                       // [B, N, T]

    expT_kernel<<<dim3(TQ / 64, BQ), 256>>>(emissions);
    fwd_kernel<<<dim3(CCH, BQ), 64>>>(trans, init);
    bwd_kernel<<<dim3(CCH, BQ), 64>>>(trans);
    gamma_kernel<<<dim3(TQ / 32, BQ), 256>>>(out);
}

// round 11
// speedup vs baseline: 1.3908x; 1.3908x over previous
#include <cuda_runtime.h>

#define BQ 64
#define NQ 64
#define TQ 4096
#define BN (BQ * NQ)     // 4096 floats per time slice
#define CCH 16           // chunks
#define LCH 256          // chunk length (CCH*LCH == TQ)

// Scratch: E = exp(emissions) in [t][b][j] layout, plus linear-domain
// alpha/beta (arbitrary per-(b,t) scale; cancels in gamma).
__device__ float g_E[TQ * BN];
__device__ float g_alpha[TQ * BN];
__device__ float g_beta[TQ * BN];

// ---- packed f32x2 helpers ----
__device__ __forceinline__ void fma2(unsigned long long& d,
                                     unsigned long long a, unsigned long long b) {
    asm("fma.rn.f32x2 %0, %1, %2, %0;" : "+l"(d) : "l"(a), "l"(b));
}
__device__ __forceinline__ unsigned long long add2(unsigned long long a,
                                                   unsigned long long b) {
    unsigned long long d;
    asm("add.rn.f32x2 %0, %1, %2;" : "=l"(d) : "l"(a), "l"(b));
    return d;
}
__device__ __forceinline__ unsigned long long pack2(float lo, float hi) {
    unsigned long long d;
    asm("mov.b64 %0, {%1, %2};" : "=l"(d) : "f"(lo), "f"(hi));
    return d;
}
__device__ __forceinline__ float2 unpack2(unsigned long long v) {
    float2 r;
    asm("mov.b64 {%0, %1}, %2;" : "=f"(r.x), "=f"(r.y) : "l"(v));
    return r;
}

// ---------------------------------------------------------------------------
// Kernel 1: E[t][b][j] = exp(emissions[b][j][t])  (tiled transpose via shared)
// ---------------------------------------------------------------------------
__global__ void __launch_bounds__(256) expT_kernel(const float* __restrict__ em) {
    __shared__ float tile[64][65];
    int b  = blockIdx.y;
    int t0 = blockIdx.x * 64;
    int tid = threadIdx.x;
    int c  = tid & 63;
    int r4 = tid >> 6;

#pragma unroll
    for (int rep = 0; rep < 16; rep++) {
        int j = rep * 4 + r4;
        tile[j][c] = __expf(em[b * NQ * TQ + j * TQ + t0 + c]);
    }
    __syncthreads();
#pragma unroll
    for (int rep = 0; rep < 16; rep++) {
        int tt = rep * 4 + r4;
        g_E[(t0 + tt) * BN + b * NQ + c] = tile[c][tt];
    }
}

// ---------------------------------------------------------------------------
// Kernel 2: chunked forward/backward scans with warmup (combined launch —
// fwd and bwd blocks run CONCURRENTLY; this concurrency is load-bearing for
// latency hiding). 64 threads, 1 state/thread, 64-term dot as 32 f32x2 FMAs.
// Interior chunks warm up 39 steps from all-ones (Hilbert contraction of A).
// Renorm every 16 steps (pairs of 8-step groups; REDUCE publishes partials in
// the 2nd group at pos+6, APPLY multiplies by 1/s at pos+7).
// E prefetch: 8 named register slots at distance 8.
// ---------------------------------------------------------------------------

#define DOT_FULL(PBUF)                                                         \
    const ulonglong2* pv = (const ulonglong2*)&psh[PBUF][0];                   \
    unsigned long long ac0 = 0, ac1 = 0, ac2 = 0, ac3 = 0;                     \
    _Pragma("unroll")                                                          \
    for (int k = 0; k < 16; k++) {                                             \
        ulonglong2 q = pv[k];                                                  \
        fma2((k & 1) ? ac2 : ac0, q.x, Apk[2 * k]);                            \
        fma2((k & 1) ? ac3 : ac1, q.y, Apk[2 * k + 1]);                        \
    }                                                                          \
    float2 fr = unpack2(add2(add2(ac0, ac1), add2(ac2, ac3)));                 \
    float v2 = fr.x + fr.y;

#define REDUCE_PUB()                                                           \
    {                                                                          \
        float s = v2;                                                          \
        s += __shfl_xor_sync(0xffffffffu, s, 1);                               \
        s += __shfl_xor_sync(0xffffffffu, s, 2);                               \
        s += __shfl_xor_sync(0xffffffffu, s, 4);                               \
        s += __shfl_xor_sync(0xffffffffu, s, 8);                               \
        s += __shfl_xor_sync(0xffffffffu, s, 16);                              \
        if (lane == 0) red[w] = s;                                             \
    }

// forward step at time T: consumes EREG = E[T]; refills with E[T+8]
#define FWD_STEP(T, EREG, APPLY, REDUCE) do {                                  \
    int tt_ = (T);                                                             \
    float e_new = g_E[((tt_ + 8 < TQ) ? tt_ + 8 : TQ - 1) * BN + ebase];       \
    if (APPLY) inv_s = __frcp_rn(red[0] + red[1]);                             \
    DOT_FULL((tt_ - 1) & 1)                                                    \
    if (APPLY) v2 *= inv_s;                                                    \
    v2 *= (EREG);                                                              \
    if (REDUCE) REDUCE_PUB()                                                   \
    if (tt_ >= wst) g_alpha[tt_ * BN + ebase] = v2;                            \
    psh[tt_ & 1][j] = v2;                                                      \
    __syncthreads();                                                           \
    (EREG) = e_new;                                                            \
} while (0)

#define FWD_G8(TB, RED) do {                                                   \
    FWD_STEP((TB),     e7, 0, 0);   FWD_STEP((TB) + 1, e0, 0, 0);              \
    FWD_STEP((TB) + 2, e1, 0, 0);   FWD_STEP((TB) + 3, e2, 0, 0);              \
    FWD_STEP((TB) + 4, e3, 0, 0);   FWD_STEP((TB) + 5, e4, 0, 0);              \
    FWD_STEP((TB) + 6, e5, 0, RED); FWD_STEP((TB) + 7, e6, RED, 0);            \
} while (0)

// backward step at time T: EREG = E[T] feeds the carry; refills with E[T-8]
#define BWD_STEP(T, EREG, APPLY, REDUCE) do {                                  \
    int tt_ = (T);                                                             \
    float e_new = g_E[((tt_ >= 8) ? tt_ - 8 : 0) * BN + ebase];                \
    if (APPLY) inv_s = __frcp_rn(red[0] + red[1]);                             \
    DOT_FULL((tt_ + 1) & 1)                                                    \
    if (APPLY) v2 *= inv_s;                                                    \
    if (REDUCE) REDUCE_PUB()                                                   \
    if (tt_ <= wend) g_beta[tt_ * BN + ebase] = v2;                            \
    psh[tt_ & 1][j] = v2 * (EREG);                                             \
    __syncthreads();                                                           \
    (EREG) = e_new;                                                            \
} while (0)

#define BWD_G8(TB, RED) do {                                                   \
    BWD_STEP((TB),     e7, 0, 0);   BWD_STEP((TB) - 1, e0, 0, 0);              \
    BWD_STEP((TB) - 2, e1, 0, 0);   BWD_STEP((TB) - 3, e2, 0, 0);              \
    BWD_STEP((TB) - 4, e3, 0, 0);   BWD_STEP((TB) - 5, e4, 0, 0);              \
    BWD_STEP((TB) - 6, e5, 0, RED); BWD_STEP((TB) - 7, e6, RED, 0);            \
} while (0)

__global__ void __launch_bounds__(64) scan_kernel(const float* __restrict__ trans,
                                                  const float* __restrict__ init) {
    const int c    = blockIdx.x;     // chunk
    const int b    = blockIdx.y;     // batch
    const int dir  = blockIdx.z;     // 0 fwd, 1 bwd
    const int j    = threadIdx.x;    // state 0..63
    const int lane = j & 31;
    const int w    = j >> 5;

    __shared__ __align__(16) float psh[2][64];
    __shared__ float red[2];

    // 64 A-coefficients per thread, packed once into 32 f32x2 registers.
    unsigned long long Apk[32];
    if (dir == 0) {
        // fwd: column j of A
#pragma unroll
        for (int k = 0; k < 16; k++) {
            int i0 = 4 * k;
            Apk[2 * k]     = pack2(trans[(i0    ) * NQ + j], trans[(i0 + 1) * NQ + j]);
            Apk[2 * k + 1] = pack2(trans[(i0 + 2) * NQ + j], trans[(i0 + 3) * NQ + j]);
        }
    } else {
        // bwd: row j of A (contiguous)
        const float4* rp = (const float4*)(trans + j * NQ);
#pragma unroll
        for (int k = 0; k < 16; k++) {
            float4 a = rp[k];
            Apk[2 * k]     = pack2(a.x, a.y);
            Apk[2 * k + 1] = pack2(a.z, a.w);
        }
    }

    const int ebase = b * NQ + j;
    float inv_s = 1.0f;

    if (dir == 0) {
        // -------- forward: write t in [c*L, (c+1)*L) --------
        const int wst = c * LCH;
        int t1, Gp, Gr;
        if (c == 0) {
            float v0 = init[j] * g_E[0 * BN + ebase];
            g_alpha[0 * BN + ebase] = v0;
            psh[0][j] = v0;
            t1 = 1;  Gp = 15;  Gr = 1;       // 7 + 31*8 = 255 steps: t = 1..255
        } else {
            t1 = c * LCH - 39;               // 39-step warmup from all-ones
            psh[(t1 - 1) & 1][j] = 1.0f;
            Gp = 18;  Gr = 0;                // 7 + 36*8 = 295 steps
        }
        float e0 = g_E[(t1    ) * BN + ebase], e1 = g_E[(t1 + 1) * BN + ebase];
        float e2 = g_E[(t1 + 2) * BN + ebase], e3 = g_E[(t1 + 3) * BN + ebase];
        float e4 = g_E[(t1 + 4) * BN + ebase], e5 = g_E[(t1 + 5) * BN + ebase];
        float e6 = g_E[(t1 + 6) * BN + ebase], e7 = g_E[(t1 + 7) * BN + ebase];
        __syncthreads();

        // INIT7 (no renorm)
        FWD_STEP(t1,     e0, 0, 0); FWD_STEP(t1 + 1, e1, 0, 0);
        FWD_STEP(t1 + 2, e2, 0, 0); FWD_STEP(t1 + 3, e3, 0, 0);
        FWD_STEP(t1 + 4, e4, 0, 0); FWD_STEP(t1 + 5, e5, 0, 0);
        FWD_STEP(t1 + 6, e6, 0, 0);

        for (int p = 0; p < Gp; p++) {       // pairs: renorm in 2nd group only
            int t = t1 + 7 + 16 * p;
            FWD_G8(t, 0); FWD_G8(t + 8, 1);
        }
        for (int g = 0; g < Gr; g++) {       // remainder groups renorm each
            int t = t1 + 7 + 16 * Gp + 8 * g;
            FWD_G8(t, 1);
        }
    } else {
        // -------- backward: write t in [c*L, (c+1)*L) --------
        const int wend = (c + 1) * LCH - 1;
        int te, Gp, Gr;
        if (c == CCH - 1) {
            te = TQ - 1;
            g_beta[te * BN + ebase] = 1.0f;
            psh[te & 1][j] = g_E[te * BN + ebase];   // carry = beta*E
            Gp = 15;  Gr = 1;                        // 255 steps
        } else {
            te = (c + 1) * LCH + 39;                 // warmup start
            psh[te & 1][j] = g_E[te * BN + ebase];   // beta = ones at te
            Gp = 18;  Gr = 0;                        // 295 steps
        }
        int t1 = te - 1;
        float e0 = g_E[(t1    ) * BN + ebase], e1 = g_E[(t1 - 1) * BN + ebase];
        float e2 = g_E[(t1 - 2) * BN + ebase], e3 = g_E[(t1 - 3) * BN + ebase];
        float e4 = g_E[(t1 - 4) * BN + ebase], e5 = g_E[(t1 - 5) * BN + ebase];
        float e6 = g_E[(t1 - 6) * BN + ebase], e7 = g_E[(t1 - 7) * BN + ebase];
        __syncthreads();

        // INIT7 (no renorm)
        BWD_STEP(t1,     e0, 0, 0); BWD_STEP(t1 - 1, e1, 0, 0);
        BWD_STEP(t1 - 2, e2, 0, 0); BWD_STEP(t1 - 3, e3, 0, 0);
        BWD_STEP(t1 - 4, e4, 0, 0); BWD_STEP(t1 - 5, e5, 0, 0);
        BWD_STEP(t1 - 6, e6, 0, 0);

        for (int p = 0; p < Gp; p++) {
            int t = t1 - 7 - 16 * p;
            BWD_G8(t, 0); BWD_G8(t - 8, 1);
        }
        for (int g = 0; g < Gr; g++) {
            int t = t1 - 7 - 16 * Gp - 8 * g;
            BWD_G8(t, 1);
        }
    }
}

// ---------------------------------------------------------------------------
// Kernel 3: gamma, linear domain. u = alpha*beta; out = log(u) - log(sum_j u).
// Scales cancel. Tiled so output writes coalesce along t.
// ---------------------------------------------------------------------------
__global__ void __launch_bounds__(256) gamma_kernel(float* __restrict__ out) {
    __shared__ float gsh[64][33];
    __shared__ float part[8][32];
    __shared__ float lse[32];

    int b   = blockIdx.y;
    int t0  = blockIdx.x * 32;
    int tid = threadIdx.x;
    int c   = tid & 63;
    int r   = tid >> 6;

#pragma unroll
    for (int rep = 0; rep < 8; rep++) {
        int tt  = rep * 4 + r;
        int idx = (t0 + tt) * BN + b * NQ + c;
        gsh[c][tt] = g_alpha[idx] * g_beta[idx];
    }
    __syncthreads();

    int tt  = tid & 31;
    int seg = tid >> 5;

    float ss = 0.f;
#pragma unroll
    for (int k = 0; k < 8; k++) ss += gsh[seg * 8 + k][tt];
    part[seg][tt] = ss;
    __syncthreads();

    if (seg == 0) {
        float s = part[0][tt];
#pragma unroll
        for (int k = 1; k < 8; k++) s += part[k][tt];
        lse[tt] = __logf(s);
    }
    __syncthreads();

    float l = lse[tt];
#pragma unroll
    for (int rep = 0; rep < 8; rep++) {
        int jj = rep * 8 + seg;
        out[b * NQ * TQ + jj * TQ + t0 + tt] = __logf(gsh[jj][tt]) - l;
    }
}

// ---------------------------------------------------------------------------
extern "C" void kernel_launch(void* const* d_in, const int* in_sizes, int n_in,
                              void* d_out, int out_size) {
    const float* emissions = (const float*)d_in[0];   // [B, N, T]
    const float* init      = (const float*)d_in[1];   // [N]
    const float* trans     = (const float*)d_in[2];   // [N, N]
    float* out = (float*)d_out;                       // [B, N, T]

    expT_kernel<<<dim3(TQ / 64, BQ), 256>>>(emissions);
    scan_kernel<<<dim3(CCH, BQ, 2), 64>>>(trans, init);
    gamma_kernel<<<dim3(TQ / 32, BQ), 256>>>(out);
}

// round 12
// speedup vs baseline: 1.5707x; 1.1293x over previous
#include <cuda_runtime.h>

#define BQ 64
#define NQ 64
#define TQ 4096
#define BN (BQ * NQ)     // 4096 floats per time slice
#define CCH 16           // chunks
#define LCH 256          // chunk length (CCH*LCH == TQ)

// Scratch: E = exp(emissions) in [t][b][j] layout, plus linear-domain
// alpha/beta (arbitrary per-(b,t) scale; cancels in gamma).
__device__ float g_E[TQ * BN];
__device__ float g_alpha[TQ * BN];
__device__ float g_beta[TQ * BN];

// ---- packed f32x2 helpers ----
__device__ __forceinline__ void fma2(unsigned long long& d,
                                     unsigned long long a, unsigned long long b) {
    asm("fma.rn.f32x2 %0, %1, %2, %0;" : "+l"(d) : "l"(a), "l"(b));
}
__device__ __forceinline__ unsigned long long add2(unsigned long long a,
                                                   unsigned long long b) {
    unsigned long long d;
    asm("add.rn.f32x2 %0, %1, %2;" : "=l"(d) : "l"(a), "l"(b));
    return d;
}
__device__ __forceinline__ unsigned long long pack2(float lo, float hi) {
    unsigned long long d;
    asm("mov.b64 %0, {%1, %2};" : "=l"(d) : "f"(lo), "f"(hi));
    return d;
}
__device__ __forceinline__ float2 unpack2(unsigned long long v) {
    float2 r;
    asm("mov.b64 {%0, %1}, %2;" : "=f"(r.x), "=f"(r.y) : "l"(v));
    return r;
}

// ---------------------------------------------------------------------------
// Kernel 1: E[t][b][j] = exp(emissions[b][j][t])  (tiled transpose via shared)
// ---------------------------------------------------------------------------
__global__ void __launch_bounds__(256) expT_kernel(const float* __restrict__ em) {
    __shared__ float tile[64][65];
    int b  = blockIdx.y;
    int t0 = blockIdx.x * 64;
    int tid = threadIdx.x;
    int c  = tid & 63;
    int r4 = tid >> 6;

#pragma unroll
    for (int rep = 0; rep < 16; rep++) {
        int j = rep * 4 + r4;
        tile[j][c] = __expf(em[b * NQ * TQ + j * TQ + t0 + c]);
    }
    __syncthreads();
#pragma unroll
    for (int rep = 0; rep < 16; rep++) {
        int tt = rep * 4 + r4;
        g_E[(t0 + tt) * BN + b * NQ + c] = tile[c][tt];
    }
}

// ---------------------------------------------------------------------------
// Kernel 2: chunked forward/backward scans with warmup (combined concurrent
// launch). 32 threads/block; thread owns ADJACENT states (2*tid, 2*tid+1):
// the 16 LDS.128 of the shared vector feed BOTH states' dots, E/alpha/psh
// accesses are 64-bit, the block is one warp (no __syncthreads; __syncwarp
// orders the psh exchange), renorm reduction is pure shfl into a register.
// Interior chunks warm up 39 steps from all-ones (Hilbert contraction of A).
// Renorm every 16 steps, pipelined (REDUCE at pair pos 14, APPLY at 15).
// E prefetch: 8 named float2 slots at distance 8.
// ---------------------------------------------------------------------------

#define DOT_BOTH(PBUF)                                                         \
    const ulonglong2* pv = (const ulonglong2*)&psh[PBUF][0];                   \
    unsigned long long aa0 = 0, aa1 = 0, bb0 = 0, bb1 = 0;                     \
    _Pragma("unroll")                                                          \
    for (int k = 0; k < 16; k++) {                                             \
        ulonglong2 q = pv[k];                                                  \
        fma2(aa0, q.x, ApkA[2 * k]); fma2(aa1, q.y, ApkA[2 * k + 1]);          \
        fma2(bb0, q.x, ApkB[2 * k]); fma2(bb1, q.y, ApkB[2 * k + 1]);          \
    }                                                                          \
    float2 fa = unpack2(add2(aa0, aa1));                                       \
    float2 fb = unpack2(add2(bb0, bb1));                                       \
    float va = fa.x + fa.y;                                                    \
    float vb = fb.x + fb.y;

#define REDUCE_SHFL()                                                          \
    {                                                                          \
        float s = va + vb;                                                     \
        s += __shfl_xor_sync(0xffffffffu, s, 1);                               \
        s += __shfl_xor_sync(0xffffffffu, s, 2);                               \
        s += __shfl_xor_sync(0xffffffffu, s, 4);                               \
        s += __shfl_xor_sync(0xffffffffu, s, 8);                               \
        s += __shfl_xor_sync(0xffffffffu, s, 16);                              \
        sred = s;                                                              \
    }

// forward step at time T: consumes EREG = E2[T]; refills with E2[T+8]
#define FWD_STEP(T, EREG, APPLY, REDUCE) do {                                  \
    int tt_ = (T);                                                             \
    float2 e_new = *(const float2*)&g_E[((tt_ + 8 < TQ) ? tt_ + 8 : TQ - 1) * BN + ebase]; \
    if (APPLY) inv_s = __frcp_rn(sred);                                        \
    DOT_BOTH((tt_ - 1) & 1)                                                    \
    if (APPLY) { va *= inv_s; vb *= inv_s; }                                   \
    va *= (EREG).x; vb *= (EREG).y;                                            \
    if (REDUCE) REDUCE_SHFL()                                                  \
    if (tt_ >= wst) *(float2*)&g_alpha[tt_ * BN + ebase] = make_float2(va, vb);\
    *(float2*)&psh[tt_ & 1][j0] = make_float2(va, vb);                         \
    __syncwarp();                                                              \
    (EREG) = e_new;                                                            \
} while (0)

#define FWD_G8(TB, RED) do {                                                   \
    FWD_STEP((TB),     e7, 0, 0);   FWD_STEP((TB) + 1, e0, 0, 0);              \
    FWD_STEP((TB) + 2, e1, 0, 0);   FWD_STEP((TB) + 3, e2, 0, 0);              \
    FWD_STEP((TB) + 4, e3, 0, 0);   FWD_STEP((TB) + 5, e4, 0, 0);              \
    FWD_STEP((TB) + 6, e5, 0, RED); FWD_STEP((TB) + 7, e6, RED, 0);            \
} while (0)

// backward step at time T: EREG = E2[T] feeds the carry; refills with E2[T-8]
#define BWD_STEP(T, EREG, APPLY, REDUCE) do {                                  \
    int tt_ = (T);                                                             \
    float2 e_new = *(const float2*)&g_E[((tt_ >= 8) ? tt_ - 8 : 0) * BN + ebase]; \
    if (APPLY) inv_s = __frcp_rn(sred);                                        \
    DOT_BOTH((tt_ + 1) & 1)                                                    \
    if (APPLY) { va *= inv_s; vb *= inv_s; }                                   \
    if (REDUCE) REDUCE_SHFL()                                                  \
    if (tt_ <= wend) *(float2*)&g_beta[tt_ * BN + ebase] = make_float2(va, vb);\
    *(float2*)&psh[tt_ & 1][j0] = make_float2(va * (EREG).x, vb * (EREG).y);   \
    __syncwarp();                                                              \
    (EREG) = e_new;                                                            \
} while (0)

#define BWD_G8(TB, RED) do {                                                   \
    BWD_STEP((TB),     e7, 0, 0);   BWD_STEP((TB) - 1, e0, 0, 0);              \
    BWD_STEP((TB) - 2, e1, 0, 0);   BWD_STEP((TB) - 3, e2, 0, 0);              \
    BWD_STEP((TB) - 4, e3, 0, 0);   BWD_STEP((TB) - 5, e4, 0, 0);              \
    BWD_STEP((TB) - 6, e5, 0, RED); BWD_STEP((TB) - 7, e6, RED, 0);            \
} while (0)

__global__ void __launch_bounds__(32) scan_kernel(const float* __restrict__ trans,
                                                  const float* __restrict__ init) {
    const int c   = blockIdx.x;      // chunk
    const int b   = blockIdx.y;      // batch
    const int dir = blockIdx.z;      // 0 fwd, 1 bwd
    const int tid = threadIdx.x;     // 0..31
    const int j0  = 2 * tid;         // first of the two owned states

    __shared__ __align__(16) float psh[2][64];

    // Two columns (fwd) or two rows (bwd) of A, packed: 64 u64 registers.
    // ApkX[2k] pairs states (4k,4k+1); ApkX[2k+1] pairs (4k+2,4k+3).
    unsigned long long ApkA[32], ApkB[32];
    if (dir == 0) {
        // fwd: columns j0, j0+1 of A
#pragma unroll
        for (int k = 0; k < 16; k++) {
            int i0 = 4 * k;
            ApkA[2 * k]     = pack2(trans[(i0    ) * NQ + j0], trans[(i0 + 1) * NQ + j0]);
            ApkA[2 * k + 1] = pack2(trans[(i0 + 2) * NQ + j0], trans[(i0 + 3) * NQ + j0]);
            ApkB[2 * k]     = pack2(trans[(i0    ) * NQ + j0 + 1], trans[(i0 + 1) * NQ + j0 + 1]);
            ApkB[2 * k + 1] = pack2(trans[(i0 + 2) * NQ + j0 + 1], trans[(i0 + 3) * NQ + j0 + 1]);
        }
    } else {
        // bwd: rows j0, j0+1 of A (contiguous)
        const float4* rA = (const float4*)(trans + j0 * NQ);
        const float4* rB = (const float4*)(trans + (j0 + 1) * NQ);
#pragma unroll
        for (int k = 0; k < 16; k++) {
            float4 a = rA[k];
            ApkA[2 * k]     = pack2(a.x, a.y);
            ApkA[2 * k + 1] = pack2(a.z, a.w);
            float4 bq = rB[k];
            ApkB[2 * k]     = pack2(bq.x, bq.y);
            ApkB[2 * k + 1] = pack2(bq.z, bq.w);
        }
    }

    const int ebase = b * NQ + j0;   // even -> float2-aligned
    float inv_s = 1.0f;
    float sred  = 1.0f;

    if (dir == 0) {
        // -------- forward: write t in [c*L, (c+1)*L) --------
        const int wst = c * LCH;
        int t1, Gp, Gr;
        if (c == 0) {
            float2 ee = *(const float2*)&g_E[0 * BN + ebase];
            float2 v0 = make_float2(init[j0] * ee.x, init[j0 + 1] * ee.y);
            *(float2*)&g_alpha[0 * BN + ebase] = v0;
            *(float2*)&psh[0][j0] = v0;
            t1 = 1;  Gp = 15;  Gr = 1;       // 7 + 31*8 = 255 steps: t = 1..255
        } else {
            t1 = c * LCH - 39;               // 39-step warmup from all-ones
            *(float2*)&psh[(t1 - 1) & 1][j0] = make_float2(1.0f, 1.0f);
            Gp = 18;  Gr = 0;                // 7 + 36*8 = 295 steps
        }
        float2 e0 = *(const float2*)&g_E[(t1    ) * BN + ebase];
        float2 e1 = *(const float2*)&g_E[(t1 + 1) * BN + ebase];
        float2 e2 = *(const float2*)&g_E[(t1 + 2) * BN + ebase];
        float2 e3 = *(const float2*)&g_E[(t1 + 3) * BN + ebase];
        float2 e4 = *(const float2*)&g_E[(t1 + 4) * BN + ebase];
        float2 e5 = *(const float2*)&g_E[(t1 + 5) * BN + ebase];
        float2 e6 = *(const float2*)&g_E[(t1 + 6) * BN + ebase];
        float2 e7 = *(const float2*)&g_E[(t1 + 7) * BN + ebase];
        __syncwarp();

        // INIT7 (no renorm)
        FWD_STEP(t1,     e0, 0, 0); FWD_STEP(t1 + 1, e1, 0, 0);
        FWD_STEP(t1 + 2, e2, 0, 0); FWD_STEP(t1 + 3, e3, 0, 0);
        FWD_STEP(t1 + 4, e4, 0, 0); FWD_STEP(t1 + 5, e5, 0, 0);
        FWD_STEP(t1 + 6, e6, 0, 0);

        for (int p = 0; p < Gp; p++) {       // pairs: renorm in 2nd group only
            int t = t1 + 7 + 16 * p;
            FWD_G8(t, 0); FWD_G8(t + 8, 1);
        }
        for (int g = 0; g < Gr; g++) {       // remainder groups renorm each
            int t = t1 + 7 + 16 * Gp + 8 * g;
            FWD_G8(t, 1);
        }
    } else {
        // -------- backward: write t in [c*L, (c+1)*L) --------
        const int wend = (c + 1) * LCH - 1;
        int te, Gp, Gr;
        if (c == CCH - 1) {
            te = TQ - 1;
            *(float2*)&g_beta[te * BN + ebase] = make_float2(1.0f, 1.0f);
            *(float2*)&psh[te & 1][j0] = *(const float2*)&g_E[te * BN + ebase];
            Gp = 15;  Gr = 1;                        // 255 steps
        } else {
            te = (c + 1) * LCH + 39;                 // warmup start
            *(float2*)&psh[te & 1][j0] = *(const float2*)&g_E[te * BN + ebase];
            Gp = 18;  Gr = 0;                        // 295 steps
        }
        int t1 = te - 1;
        float2 e0 = *(const float2*)&g_E[(t1    ) * BN + ebase];
        float2 e1 = *(const float2*)&g_E[(t1 - 1) * BN + ebase];
        float2 e2 = *(const float2*)&g_E[(t1 - 2) * BN + ebase];
        float2 e3 = *(const float2*)&g_E[(t1 - 3) * BN + ebase];
        float2 e4 = *(const float2*)&g_E[(t1 - 4) * BN + ebase];
        float2 e5 = *(const float2*)&g_E[(t1 - 5) * BN + ebase];
        float2 e6 = *(const float2*)&g_E[(t1 - 6) * BN + ebase];
        float2 e7 = *(const float2*)&g_E[(t1 - 7) * BN + ebase];
        __syncwarp();

        // INIT7 (no renorm)
        BWD_STEP(t1,     e0, 0, 0); BWD_STEP(t1 - 1, e1, 0, 0);
        BWD_STEP(t1 - 2, e2, 0, 0); BWD_STEP(t1 - 3, e3, 0, 0);
        BWD_STEP(t1 - 4, e4, 0, 0); BWD_STEP(t1 - 5, e5, 0, 0);
        BWD_STEP(t1 - 6, e6, 0, 0);

        for (int p = 0; p < Gp; p++) {
            int t = t1 - 7 - 16 * p;
            BWD_G8(t, 0); BWD_G8(t - 8, 1);
        }
        for (int g = 0; g < Gr; g++) {
            int t = t1 - 7 - 16 * Gp - 8 * g;
            BWD_G8(t, 1);
        }
    }
}

// ---------------------------------------------------------------------------
// Kernel 3: gamma, linear domain. u = alpha*beta; out = log(u) - log(sum_j u).
// Scales cancel. Tiled so output writes coalesce along t.
// ---------------------------------------------------------------------------
__global__ void __launch_bounds__(256) gamma_kernel(float* __restrict__ out) {
    __shared__ float gsh[64][33];
    __shared__ float part[8][32];
    __shared__ float lse[32];

    int b   = blockIdx.y;
    int t0  = blockIdx.x * 32;
    int tid = threadIdx.x;
    int c   = tid & 63;
    int r   = tid >> 6;

#pragma unroll
    for (int rep = 0; rep < 8; rep++) {
        int tt  = rep * 4 + r;
        int idx = (t0 + tt) * BN + b * NQ + c;
        gsh[c][tt] = g_alpha[idx] * g_beta[idx];
    }
    __syncthreads();

    int tt  = tid & 31;
    int seg = tid >> 5;

    float ss = 0.f;
#pragma unroll
    for (int k = 0; k < 8; k++) ss += gsh[seg * 8 + k][tt];
    part[seg][tt] = ss;
    __syncthreads();

    if (seg == 0) {
        float s = part[0][tt];
#pragma unroll
        for (int k = 1; k < 8; k++) s += part[k][tt];
        lse[tt] = __logf(s);
    }
    __syncthreads();

    float l = lse[tt];
#pragma unroll
    for (int rep = 0; rep < 8; rep++) {
        int jj = rep * 8 + seg;
        out[b * NQ * TQ + jj * TQ + t0 + tt] = __logf(gsh[jj][tt]) - l;
    }
}

// ---------------------------------------------------------------------------
extern "C" void kernel_launch(void* const* d_in, const int* in_sizes, int n_in,
                              void* d_out, int out_size) {
    const float* emissions = (const float*)d_in[0];   // [B, N, T]
    const float* init      = (const float*)d_in[1];   // [N]
    const float* trans     = (const float*)d_in[2];   // [N, N]
    float* out = (float*)d_out;                       // [B, N, T]

    expT_kernel<<<dim3(TQ / 64, BQ), 256>>>(emissions);
    scan_kernel<<<dim3(CCH, BQ, 2), 32>>>(trans, init);
    gamma_kernel<<<dim3(TQ / 32, BQ), 256>>>(out);
}